// round 6
// baseline (speedup 1.0000x reference)
#include <cuda_runtime.h>
#include <cuda_bf16.h>

#define N_NODES 50000
#define N_EDGES 800000
#define DIM 128

// ---------------- device scratch (no allocations allowed) ----------------
__device__ int   g_count[N_NODES];        // histogram, then reused as scatter cursor
__device__ int   g_rowptr[N_NODES + 1];
__device__ int   g_esrc[N_EDGES];
__device__ float g_agg[N_NODES * DIM];
__device__ float g_h1[N_NODES * DIM];
__device__ float g_h2[N_NODES * DIM];

// ---------------- CSR build ----------------
__global__ void zero_count_kernel() {
    int i = blockIdx.x * blockDim.x + threadIdx.x;
    if (i < N_NODES) g_count[i] = 0;
}

__global__ void hist_kernel(const int* __restrict__ dst) {
    int e = blockIdx.x * blockDim.x + threadIdx.x;
    if (e < N_EDGES) {
        unsigned d = (unsigned)dst[e];
        if (d < N_NODES) atomicAdd(&g_count[d], 1);   // value clamp: never fault
    }
}

// single-block scan (1024 threads), Hillis-Steele per 1024-chunk with running carry
__global__ void scan_kernel() {
    __shared__ int sh[1024];
    __shared__ int carry;
    int t = threadIdx.x;
    if (t == 0) { carry = 0; g_rowptr[0] = 0; }
    __syncthreads();
    for (int base = 0; base < N_NODES; base += 1024) {
        int v = (base + t < N_NODES) ? g_count[base + t] : 0;
        sh[t] = v;
        __syncthreads();
        for (int off = 1; off < 1024; off <<= 1) {
            int x = (t >= off) ? sh[t - off] : 0;
            __syncthreads();
            sh[t] += x;
            __syncthreads();
        }
        if (base + t < N_NODES) g_rowptr[base + t + 1] = carry + sh[t];
        __syncthreads();
        if (t == 0) carry += sh[1023];
        __syncthreads();
    }
}

__global__ void cursor_kernel() {
    int i = blockIdx.x * blockDim.x + threadIdx.x;
    if (i < N_NODES) g_count[i] = g_rowptr[i];
}

__global__ void scatter_kernel(const int* __restrict__ src, const int* __restrict__ dst) {
    int e = blockIdx.x * blockDim.x + threadIdx.x;
    if (e < N_EDGES) {
        unsigned d = (unsigned)dst[e];
        unsigned s = (unsigned)src[e];
        if (d < N_NODES && s < N_NODES) {
            int pos = atomicAdd(&g_count[d], 1);
            if ((unsigned)pos < N_EDGES) g_esrc[pos] = (int)s;
        }
    }
}

// ---------------- mean aggregation: one warp per node ----------------
// HSEL: 0 = external pointer (x), 1 = g_h1, 2 = g_h2. Output: g_agg (by symbol).
template <int HSEL>
__global__ void aggregate_kernel(const float* __restrict__ hext) {
    const float* __restrict__ h =
        (HSEL == 0) ? hext : ((HSEL == 1) ? (const float*)g_h1 : (const float*)g_h2);
    int warp = (blockIdx.x * blockDim.x + threadIdx.x) >> 5;
    int lane = threadIdx.x & 31;
    if (warp >= N_NODES) return;
    int beg = g_rowptr[warp];
    int end = g_rowptr[warp + 1];
    float ax = 0.f, ay = 0.f, az = 0.f, aw = 0.f;
    for (int i = beg; i < end; i++) {
        int s = g_esrc[i];
        float4 v = *reinterpret_cast<const float4*>(&h[(size_t)s * DIM + lane * 4]);
        ax += v.x; ay += v.y; az += v.z; aw += v.w;
    }
    float inv = (end > beg) ? (1.0f / (float)(end - beg)) : 0.0f;
    float4 r; r.x = ax * inv; r.y = ay * inv; r.z = az * inv; r.w = aw * inv;
    *reinterpret_cast<float4*>(&g_agg[(size_t)warp * DIM + lane * 4]) = r;
}

// ---------------- fused GEMM: out = act([h|agg] @ [Wself;Wneigh] + b) ----------------
// Block = 256 threads, tile = 64 nodes x OUT outputs, K = 256.
// Generic thread mapping: OG = OUT/8 output groups of 8 cols; NPT = OUT/32 nodes/thread.
//   OUT=128: 16 groups x 4 nodes (og=t&15).  OUT=64: 8 groups x 2 nodes (og=t&7).
// HSEL selects input buffer (0=ext,1=g_h1,2=g_h2); DSEL selects output (0=ext,1=g_h1,2=g_h2).
template <int OUT, bool RELU, int HSEL, int DSEL>
__global__ __launch_bounds__(256)
void gemm_kernel(const float* __restrict__ hinext,
                 const float* __restrict__ Wself, const float* __restrict__ Wneigh,
                 const float* __restrict__ bias, float* __restrict__ outext) {
    const float* __restrict__ hin =
        (HSEL == 0) ? hinext : ((HSEL == 1) ? (const float*)g_h1 : (const float*)g_h2);
    float* __restrict__ out =
        (DSEL == 0) ? outext : ((DSEL == 1) ? (float*)g_h1 : (float*)g_h2);

    extern __shared__ float smem[];
    float* wsm = smem;                 // [256][OUT]
    float* inT = smem + 256 * OUT;     // [256][64] (K-major transposed input tile)
    float* bs  = inT + 256 * 64;       // [OUT]

    int t = threadIdx.x;
    int node0 = blockIdx.x * 64;

    // load weights: rows 0..127 = Wself, rows 128..255 = Wneigh
    {
        const float4* Wsv = reinterpret_cast<const float4*>(Wself);
        const float4* Wnv = reinterpret_cast<const float4*>(Wneigh);
        float4* wv = reinterpret_cast<float4*>(wsm);
        const int q = 128 * OUT / 4;
        for (int i = t; i < q; i += 256) wv[i] = Wsv[i];
        for (int i = t; i < q; i += 256) wv[q + i] = Wnv[i];
        if (t < OUT) bs[t] = bias[t];
    }

    // load input tile transposed: inT[k][j] for j in [0,64), k in [0,256)
    {
        const float4 z4 = make_float4(0.f, 0.f, 0.f, 0.f);
        for (int i = t; i < 64 * 32; i += 256) {   // 64 nodes * 32 float4 per 128-dim row
            int j  = i >> 5;
            int k4 = i & 31;
            int n  = node0 + j;
            float4 v = (n < N_NODES)
                ? *reinterpret_cast<const float4*>(&hin[(size_t)n * DIM + k4 * 4]) : z4;
            float4 u = (n < N_NODES)
                ? *reinterpret_cast<const float4*>(&g_agg[(size_t)n * DIM + k4 * 4]) : z4;
            int kb = k4 * 4;
            inT[(kb + 0) * 64 + j] = v.x;
            inT[(kb + 1) * 64 + j] = v.y;
            inT[(kb + 2) * 64 + j] = v.z;
            inT[(kb + 3) * 64 + j] = v.w;
            inT[(128 + kb + 0) * 64 + j] = u.x;
            inT[(128 + kb + 1) * 64 + j] = u.y;
            inT[(128 + kb + 2) * 64 + j] = u.z;
            inT[(128 + kb + 3) * 64 + j] = u.w;
        }
    }
    __syncthreads();

    constexpr int OG  = OUT / 8;       // output groups (16 for OUT=128, 8 for OUT=64)
    constexpr int NPT = OUT / 32;      // nodes per thread (4 / 2)
    const int og  = t % OG;
    const int ng  = t / OG;
    const int o0  = og * 8;            // < OUT always
    const int n0b = ng * NPT;          // < 64 always

    float acc[NPT][8];
#pragma unroll
    for (int ni = 0; ni < NPT; ni++)
#pragma unroll
        for (int oi = 0; oi < 8; oi++) acc[ni][oi] = 0.f;

    for (int k = 0; k < 256; k += 4) {
#pragma unroll
        for (int kk = 0; kk < 4; kk++) {
            float av[NPT];
            if constexpr (NPT == 4) {
                const float4 a = *reinterpret_cast<const float4*>(&inT[(k + kk) * 64 + n0b]);
                av[0] = a.x; av[1] = a.y; av[2] = a.z; av[3] = a.w;
            } else {
                const float2 a = *reinterpret_cast<const float2*>(&inT[(k + kk) * 64 + n0b]);
                av[0] = a.x; av[1] = a.y;
            }
            const float4 w0 = *reinterpret_cast<const float4*>(&wsm[(k + kk) * OUT + o0]);
            const float4 w1 = *reinterpret_cast<const float4*>(&wsm[(k + kk) * OUT + o0 + 4]);
            float wv[8] = {w0.x, w0.y, w0.z, w0.w, w1.x, w1.y, w1.z, w1.w};
#pragma unroll
            for (int ni = 0; ni < NPT; ni++)
#pragma unroll
                for (int oi = 0; oi < 8; oi++)
                    acc[ni][oi] = fmaf(av[ni], wv[oi], acc[ni][oi]);
        }
    }

#pragma unroll
    for (int ni = 0; ni < NPT; ni++) {
        int n = node0 + n0b + ni;
        if (n < N_NODES) {
            float4 r0, r1;
            r0.x = acc[ni][0] + bs[o0 + 0];
            r0.y = acc[ni][1] + bs[o0 + 1];
            r0.z = acc[ni][2] + bs[o0 + 2];
            r0.w = acc[ni][3] + bs[o0 + 3];
            r1.x = acc[ni][4] + bs[o0 + 4];
            r1.y = acc[ni][5] + bs[o0 + 5];
            r1.z = acc[ni][6] + bs[o0 + 6];
            r1.w = acc[ni][7] + bs[o0 + 7];
            if (RELU) {
                r0.x = fmaxf(r0.x, 0.f); r0.y = fmaxf(r0.y, 0.f);
                r0.z = fmaxf(r0.z, 0.f); r0.w = fmaxf(r0.w, 0.f);
                r1.x = fmaxf(r1.x, 0.f); r1.y = fmaxf(r1.y, 0.f);
                r1.z = fmaxf(r1.z, 0.f); r1.w = fmaxf(r1.w, 0.f);
            }
            *reinterpret_cast<float4*>(&out[(size_t)n * OUT + o0])     = r0;
            *reinterpret_cast<float4*>(&out[(size_t)n * OUT + o0 + 4]) = r1;
        }
    }
}

// ---------------- host launcher ----------------
extern "C" void kernel_launch(void* const* d_in, const int* in_sizes, int n_in,
                              void* d_out, int out_size) {
    // --- size-class input identification (ordering-agnostic, fault-proof) ---
    // Size classes: x=6400000 (unique), edges=800000 (x2), W01=16384 (x4),
    //               W2=8192 (x2), b01=128 (x2), b2=64 (unique).
    const float* x = nullptr;
    const int*   edge[2] = {nullptr, nullptr};
    const float* w16[4]  = {nullptr, nullptr, nullptr, nullptr};
    const float* w8[2]   = {nullptr, nullptr};
    const float* b128[2] = {nullptr, nullptr};
    const float* b2 = nullptr;
    int ne = 0, n16 = 0, n8 = 0, nb = 0;
    int x_slot = -1;

    for (int i = 0; i < n_in && i < 12; i++) {
        int sz = in_sizes[i];
        if (sz == N_NODES * DIM)      { x = (const float*)d_in[i]; x_slot = i; }
        else if (sz == N_EDGES)       { if (ne < 2)  edge[ne++] = (const int*)d_in[i]; }
        else if (sz == DIM * DIM)     { if (n16 < 4) w16[n16++] = (const float*)d_in[i]; }
        else if (sz == DIM * 64)      { if (n8 < 2)  w8[n8++]   = (const float*)d_in[i]; }
        else if (sz == DIM)           { if (nb < 2)  b128[nb++] = (const float*)d_in[i]; }
        else if (sz == 64)            { b2 = (const float*)d_in[i]; }
    }

    const float *Ws0, *Wn0, *b0, *Ws1, *Wn1, *b1, *Ws2, *Wn2;
    const int *src, *dst;
    if (x_slot == 0) {
        // insertion order: x, src, dst, W_self0, W_neigh0, b0, W_self1, W_neigh1, b1, ...
        src = edge[0]; dst = edge[1];
        Ws0 = w16[0]; Wn0 = w16[1]; Ws1 = w16[2]; Wn1 = w16[3];
        Ws2 = w8[0];  Wn2 = w8[1];
    } else {
        // lexicographic family: W_neigh* before W_self*, dst before src
        dst = edge[0]; src = edge[1];
        Wn0 = w16[0]; Wn1 = w16[1]; Ws0 = w16[2]; Ws1 = w16[3];
        Wn2 = w8[0];  Ws2 = w8[1];
    }
    b0 = b128[0]; b1 = b128[1];
    float* out = (float*)d_out;

    const int SMEM128 = (256 * 128 + 256 * 64 + 128) * 4;  // 197120
    const int SMEM64  = (256 * 64 + 256 * 64 + 64) * 4;    // 131328
    cudaFuncSetAttribute(gemm_kernel<128, true, 0, 1>,
                         cudaFuncAttributeMaxDynamicSharedMemorySize, SMEM128);
    cudaFuncSetAttribute(gemm_kernel<128, true, 1, 2>,
                         cudaFuncAttributeMaxDynamicSharedMemorySize, SMEM128);
    cudaFuncSetAttribute(gemm_kernel<64, false, 2, 0>,
                         cudaFuncAttributeMaxDynamicSharedMemorySize, SMEM64);

    // ---- CSR build (by dst) ----
    zero_count_kernel<<<(N_NODES + 255) / 256, 256>>>();
    hist_kernel<<<(N_EDGES + 255) / 256, 256>>>(dst);
    scan_kernel<<<1, 1024>>>();
    cursor_kernel<<<(N_NODES + 255) / 256, 256>>>();
    scatter_kernel<<<(N_EDGES + 255) / 256, 256>>>(src, dst);

    const int AGG_BLOCKS  = (N_NODES * 32 + 255) / 256;   // one warp per node
    const int GEMM_BLOCKS = (N_NODES + 63) / 64;

    // ---- layer 0: x -> g_h1 ----
    aggregate_kernel<0><<<AGG_BLOCKS, 256>>>(x);
    gemm_kernel<128, true, 0, 1><<<GEMM_BLOCKS, 256, SMEM128>>>(x, Ws0, Wn0, b0, nullptr);

    // ---- layer 1: g_h1 -> g_h2 ----
    aggregate_kernel<1><<<AGG_BLOCKS, 256>>>(nullptr);
    gemm_kernel<128, true, 1, 2><<<GEMM_BLOCKS, 256, SMEM128>>>(nullptr, Ws1, Wn1, b1, nullptr);

    // ---- layer 2: g_h2 -> out ----
    aggregate_kernel<2><<<AGG_BLOCKS, 256>>>(nullptr);
    gemm_kernel<64, false, 2, 0><<<GEMM_BLOCKS, 256, SMEM64>>>(nullptr, Ws2, Wn2, b2, out);
}

// round 7
// speedup vs baseline: 1.9759x; 1.9759x over previous
#include <cuda_runtime.h>
#include <cuda_bf16.h>

#define N_NODES 50000
#define N_EDGES 800000
#define DIM 128

// ---------------- device scratch (no allocations allowed) ----------------
__device__ int   g_count[N_NODES];
__device__ int   g_rowptr[N_NODES + 1];
__device__ int   g_esrc[N_EDGES];
__device__ float g_agg[N_NODES * DIM];
__device__ float g_h1[N_NODES * DIM];
__device__ float g_h2[N_NODES * DIM];

// ---------------- CSR build ----------------
__global__ void zero_count_kernel() {
    int i = blockIdx.x * blockDim.x + threadIdx.x;
    if (i < N_NODES) g_count[i] = 0;
}

__global__ void hist_kernel(const int* __restrict__ dst) {
    int e = blockIdx.x * blockDim.x + threadIdx.x;
    if (e < N_EDGES) {
        unsigned d = (unsigned)dst[e];
        if (d < N_NODES) atomicAdd(&g_count[d], 1);
    }
}

// single-block scan: shfl warp-scan, 4 syncs per 1024-chunk
__global__ void scan_kernel() {
    __shared__ int wsum[32];
    __shared__ int carry_s;
    int t = threadIdx.x, lane = t & 31, w = t >> 5;
    if (t == 0) { carry_s = 0; g_rowptr[0] = 0; }
    __syncthreads();
    for (int base = 0; base < N_NODES; base += 1024) {
        int v = (base + t < N_NODES) ? g_count[base + t] : 0;
        int s = v;
#pragma unroll
        for (int off = 1; off < 32; off <<= 1) {
            int x = __shfl_up_sync(0xFFFFFFFFu, s, off);
            if (lane >= off) s += x;
        }
        if (lane == 31) wsum[w] = s;
        __syncthreads();
        if (w == 0) {
            int ws = wsum[lane];
#pragma unroll
            for (int off = 1; off < 32; off <<= 1) {
                int x = __shfl_up_sync(0xFFFFFFFFu, ws, off);
                if (lane >= off) ws += x;
            }
            wsum[lane] = ws;
        }
        __syncthreads();
        int excl_warp = (w == 0) ? 0 : wsum[w - 1];
        int total = wsum[31];
        if (base + t < N_NODES) g_rowptr[base + t + 1] = carry_s + excl_warp + s;
        __syncthreads();
        if (t == 0) carry_s += total;
        __syncthreads();
    }
}

__global__ void cursor_kernel() {
    int i = blockIdx.x * blockDim.x + threadIdx.x;
    if (i < N_NODES) g_count[i] = g_rowptr[i];
}

__global__ void scatter_kernel(const int* __restrict__ src, const int* __restrict__ dst) {
    int e = blockIdx.x * blockDim.x + threadIdx.x;
    if (e < N_EDGES) {
        unsigned d = (unsigned)dst[e];
        unsigned s = (unsigned)src[e];
        if (d < N_NODES && s < N_NODES) {
            int pos = atomicAdd(&g_count[d], 1);
            if ((unsigned)pos < N_EDGES) g_esrc[pos] = (int)s;
        }
    }
}

// ---------------- mean aggregation: one warp per node ----------------
template <int HSEL>
__global__ void aggregate_kernel(const float* __restrict__ hext) {
    const float* __restrict__ h =
        (HSEL == 0) ? hext : ((HSEL == 1) ? (const float*)g_h1 : (const float*)g_h2);
    int warp = (blockIdx.x * blockDim.x + threadIdx.x) >> 5;
    int lane = threadIdx.x & 31;
    if (warp >= N_NODES) return;
    int beg = g_rowptr[warp];
    int end = g_rowptr[warp + 1];
    float ax = 0.f, ay = 0.f, az = 0.f, aw = 0.f;
    for (int i = beg; i < end; i++) {
        int s = g_esrc[i];
        float4 v = *reinterpret_cast<const float4*>(&h[(size_t)s * DIM + lane * 4]);
        ax += v.x; ay += v.y; az += v.z; aw += v.w;
    }
    float inv = (end > beg) ? (1.0f / (float)(end - beg)) : 0.0f;
    float4 r; r.x = ax * inv; r.y = ay * inv; r.z = az * inv; r.w = aw * inv;
    *reinterpret_cast<float4*>(&g_agg[(size_t)warp * DIM + lane * 4]) = r;
}

// ---------------- fused GEMM v3: K-tiled, high occupancy ----------------
// out[n][o] = act( sum_k [h|agg][n][k] * [Wself;Wneigh][k][o] + b[o] )
// Block: 256 threads (8 warps), tile J=64 nodes x OUT cols, K tiled by KT=64.
// Warp w owns cols [w*OUT/8, (w+1)*OUT/8); lane owns nodes {lane, lane+32}.
// smem: wT[KT][OUT] (copied k-major, conflict-free), inT[KT][65] (padded
// transpose, conflict-free scalar writes and lane-indexed reads), bs[OUT].
template <int OUT, bool RELU, int HSEL, int DSEL>
__global__ __launch_bounds__(256)
void gemm_kernel(const float* __restrict__ hinext,
                 const float* __restrict__ Wself, const float* __restrict__ Wneigh,
                 const float* __restrict__ bias, float* __restrict__ outext) {
    const float* __restrict__ hin =
        (HSEL == 0) ? hinext : ((HSEL == 1) ? (const float*)g_h1 : (const float*)g_h2);
    float* __restrict__ out =
        (DSEL == 0) ? outext : ((DSEL == 1) ? (float*)g_h1 : (float*)g_h2);

    constexpr int KT   = 64;
    constexpr int J    = 64;
    constexpr int IPAD = J + 1;            // 65: conflict-free transpose
    constexpr int WC   = OUT / 8;          // cols per warp (16 for 128, 8 for 64)

    extern __shared__ float smem[];
    float* wT  = smem;                     // [KT][OUT]
    float* inT = smem + KT * OUT;          // [KT][IPAD]
    float* bs  = inT + KT * IPAD;          // [OUT]

    const int t     = threadIdx.x;
    const int lane  = t & 31;
    const int wid   = t >> 5;
    const int wcol0 = wid * WC;
    const int node0 = blockIdx.x * J;

    if (t < OUT) bs[t] = bias[t];

    float acc[2][WC];
#pragma unroll
    for (int ni = 0; ni < 2; ni++)
#pragma unroll
        for (int c = 0; c < WC; c++) acc[ni][c] = 0.f;

    for (int kt = 0; kt < 4; kt++) {
        const int k0 = kt * KT;
        // ---- load weight tile: contiguous rows k0..k0+63 of Wself or Wneigh ----
        {
            const float* Wrow = (k0 < 128) ? (Wself + (size_t)k0 * OUT)
                                           : (Wneigh + (size_t)(k0 - 128) * OUT);
            const float4* wsrc = reinterpret_cast<const float4*>(Wrow);
            float4* wdst = reinterpret_cast<float4*>(wT);
            constexpr int NW4 = KT * OUT / 4;
#pragma unroll
            for (int i = t; i < NW4; i += 256) wdst[i] = wsrc[i];
        }
        // ---- load input tile transposed: inT[k][j] = src[node0+j][k0+k] ----
        {
            const float* srcb = (k0 < 128) ? hin : (const float*)g_agg;
            const int koff = (k0 < 128) ? k0 : (k0 - 128);
            const float4 z4 = make_float4(0.f, 0.f, 0.f, 0.f);
#pragma unroll
            for (int i = t; i < J * (KT / 4); i += 256) {   // 64*16 = 1024
                int j  = i >> 4;
                int k4 = i & 15;
                int n  = node0 + j;
                float4 v = (n < N_NODES)
                    ? *reinterpret_cast<const float4*>(&srcb[(size_t)n * DIM + koff + k4 * 4])
                    : z4;
                int kb = k4 * 4;
                inT[(kb + 0) * IPAD + j] = v.x;
                inT[(kb + 1) * IPAD + j] = v.y;
                inT[(kb + 2) * IPAD + j] = v.z;
                inT[(kb + 3) * IPAD + j] = v.w;
            }
        }
        __syncthreads();

        // ---- compute ----
#pragma unroll 4
        for (int k = 0; k < KT; k++) {
            float a0 = inT[k * IPAD + lane];
            float a1 = inT[k * IPAD + 32 + lane];
            const float* wrow = &wT[k * OUT + wcol0];
#pragma unroll
            for (int c4 = 0; c4 < WC / 4; c4++) {
                float4 wv = *reinterpret_cast<const float4*>(&wrow[c4 * 4]);
                acc[0][c4 * 4 + 0] = fmaf(a0, wv.x, acc[0][c4 * 4 + 0]);
                acc[0][c4 * 4 + 1] = fmaf(a0, wv.y, acc[0][c4 * 4 + 1]);
                acc[0][c4 * 4 + 2] = fmaf(a0, wv.z, acc[0][c4 * 4 + 2]);
                acc[0][c4 * 4 + 3] = fmaf(a0, wv.w, acc[0][c4 * 4 + 3]);
                acc[1][c4 * 4 + 0] = fmaf(a1, wv.x, acc[1][c4 * 4 + 0]);
                acc[1][c4 * 4 + 1] = fmaf(a1, wv.y, acc[1][c4 * 4 + 1]);
                acc[1][c4 * 4 + 2] = fmaf(a1, wv.z, acc[1][c4 * 4 + 2]);
                acc[1][c4 * 4 + 3] = fmaf(a1, wv.w, acc[1][c4 * 4 + 3]);
            }
        }
        __syncthreads();
    }

    // ---- epilogue: bias + act + store ----
#pragma unroll
    for (int ni = 0; ni < 2; ni++) {
        int n = node0 + lane + ni * 32;
        if (n < N_NODES) {
#pragma unroll
            for (int c4 = 0; c4 < WC / 4; c4++) {
                float4 r;
                r.x = acc[ni][c4 * 4 + 0] + bs[wcol0 + c4 * 4 + 0];
                r.y = acc[ni][c4 * 4 + 1] + bs[wcol0 + c4 * 4 + 1];
                r.z = acc[ni][c4 * 4 + 2] + bs[wcol0 + c4 * 4 + 2];
                r.w = acc[ni][c4 * 4 + 3] + bs[wcol0 + c4 * 4 + 3];
                if (RELU) {
                    r.x = fmaxf(r.x, 0.f); r.y = fmaxf(r.y, 0.f);
                    r.z = fmaxf(r.z, 0.f); r.w = fmaxf(r.w, 0.f);
                }
                *reinterpret_cast<float4*>(&out[(size_t)n * OUT + wcol0 + c4 * 4]) = r;
            }
        }
    }
}

// ---------------- host launcher ----------------
extern "C" void kernel_launch(void* const* d_in, const int* in_sizes, int n_in,
                              void* d_out, int out_size) {
    // size-class input identification (ordering-agnostic)
    const float* x = nullptr;
    const int*   edge[2] = {nullptr, nullptr};
    const float* w16[4]  = {nullptr, nullptr, nullptr, nullptr};
    const float* w8[2]   = {nullptr, nullptr};
    const float* b128[2] = {nullptr, nullptr};
    const float* b2 = nullptr;
    int ne = 0, n16 = 0, n8 = 0, nb = 0;
    int x_slot = -1;

    for (int i = 0; i < n_in && i < 12; i++) {
        int sz = in_sizes[i];
        if (sz == N_NODES * DIM)      { x = (const float*)d_in[i]; x_slot = i; }
        else if (sz == N_EDGES)       { if (ne < 2)  edge[ne++] = (const int*)d_in[i]; }
        else if (sz == DIM * DIM)     { if (n16 < 4) w16[n16++] = (const float*)d_in[i]; }
        else if (sz == DIM * 64)      { if (n8 < 2)  w8[n8++]   = (const float*)d_in[i]; }
        else if (sz == DIM)           { if (nb < 2)  b128[nb++] = (const float*)d_in[i]; }
        else if (sz == 64)            { b2 = (const float*)d_in[i]; }
    }

    const float *Ws0, *Wn0, *b0, *Ws1, *Wn1, *b1, *Ws2, *Wn2;
    const int *src, *dst;
    if (x_slot == 0) {
        // insertion order: x, src, dst, W_self0, W_neigh0, b0, W_self1, ...
        src = edge[0]; dst = edge[1];
        Ws0 = w16[0]; Wn0 = w16[1]; Ws1 = w16[2]; Wn1 = w16[3];
        Ws2 = w8[0];  Wn2 = w8[1];
    } else {
        // lexicographic family: W_neigh* before W_self*, dst before src
        dst = edge[0]; src = edge[1];
        Wn0 = w16[0]; Wn1 = w16[1]; Ws0 = w16[2]; Ws1 = w16[3];
        Wn2 = w8[0];  Ws2 = w8[1];
    }
    b0 = b128[0]; b1 = b128[1];
    float* out = (float*)d_out;

    // smem sizes: wT(KT*OUT) + inT(KT*65) + bs(OUT), floats
    const int SMEM128 = (64 * 128 + 64 * 65 + 128) * 4;   // 49920 B
    const int SMEM64  = (64 * 64 + 64 * 65 + 64) * 4;     // 33280 B
    cudaFuncSetAttribute(gemm_kernel<128, true, 0, 1>,
                         cudaFuncAttributeMaxDynamicSharedMemorySize, SMEM128);
    cudaFuncSetAttribute(gemm_kernel<128, true, 1, 2>,
                         cudaFuncAttributeMaxDynamicSharedMemorySize, SMEM128);
    cudaFuncSetAttribute(gemm_kernel<64, false, 2, 0>,
                         cudaFuncAttributeMaxDynamicSharedMemorySize, SMEM64);

    // ---- CSR build (by dst) ----
    zero_count_kernel<<<(N_NODES + 255) / 256, 256>>>();
    hist_kernel<<<(N_EDGES + 255) / 256, 256>>>(dst);
    scan_kernel<<<1, 1024>>>();
    cursor_kernel<<<(N_NODES + 255) / 256, 256>>>();
    scatter_kernel<<<(N_EDGES + 255) / 256, 256>>>(src, dst);

    const int AGG_BLOCKS  = (N_NODES * 32 + 255) / 256;   // one warp per node
    const int GEMM_BLOCKS = (N_NODES + 63) / 64;

    // ---- layer 0: x -> g_h1 ----
    aggregate_kernel<0><<<AGG_BLOCKS, 256>>>(x);
    gemm_kernel<128, true, 0, 1><<<GEMM_BLOCKS, 256, SMEM128>>>(x, Ws0, Wn0, b0, nullptr);

    // ---- layer 1: g_h1 -> g_h2 ----
    aggregate_kernel<1><<<AGG_BLOCKS, 256>>>(nullptr);
    gemm_kernel<128, true, 1, 2><<<GEMM_BLOCKS, 256, SMEM128>>>(nullptr, Ws1, Wn1, b1, nullptr);

    // ---- layer 2: g_h2 -> out ----
    aggregate_kernel<2><<<AGG_BLOCKS, 256>>>(nullptr);
    gemm_kernel<64, false, 2, 0><<<GEMM_BLOCKS, 256, SMEM64>>>(nullptr, Ws2, Wn2, b2, out);
}

// round 8
// speedup vs baseline: 1.9767x; 1.0004x over previous
#include <cuda_runtime.h>
#include <cuda_bf16.h>

#define N_NODES 50000
#define N_EDGES 800000
#define DIM 128

typedef unsigned long long u64;

// packed f32x2 fma: acc = a*b + acc (element-wise on 2 packed floats)
#define FMA_F32X2(acc, a, b) \
    asm("fma.rn.f32x2 %0, %1, %2, %0;" : "+l"(acc) : "l"(a), "l"(b))

// ---------------- device scratch (no allocations allowed) ----------------
__device__ int   g_count[N_NODES];
__device__ int   g_rowptr[N_NODES + 1];
__device__ int   g_esrc[N_EDGES];
__device__ float g_agg[N_NODES * DIM];
__device__ float g_h1[N_NODES * DIM];
__device__ float g_h2[N_NODES * DIM];

// ---------------- CSR build ----------------
__global__ void zero_count_kernel() {
    int i = blockIdx.x * blockDim.x + threadIdx.x;
    if (i < N_NODES) g_count[i] = 0;
}

__global__ void hist_kernel(const int* __restrict__ dst) {
    int e = blockIdx.x * blockDim.x + threadIdx.x;
    if (e < N_EDGES) {
        unsigned d = (unsigned)dst[e];
        if (d < N_NODES) atomicAdd(&g_count[d], 1);
    }
}

// single-block scan: shfl warp-scan, 4 syncs per 1024-chunk
__global__ void scan_kernel() {
    __shared__ int wsum[32];
    __shared__ int carry_s;
    int t = threadIdx.x, lane = t & 31, w = t >> 5;
    if (t == 0) { carry_s = 0; g_rowptr[0] = 0; }
    __syncthreads();
    for (int base = 0; base < N_NODES; base += 1024) {
        int v = (base + t < N_NODES) ? g_count[base + t] : 0;
        int s = v;
#pragma unroll
        for (int off = 1; off < 32; off <<= 1) {
            int x = __shfl_up_sync(0xFFFFFFFFu, s, off);
            if (lane >= off) s += x;
        }
        if (lane == 31) wsum[w] = s;
        __syncthreads();
        if (w == 0) {
            int ws = wsum[lane];
#pragma unroll
            for (int off = 1; off < 32; off <<= 1) {
                int x = __shfl_up_sync(0xFFFFFFFFu, ws, off);
                if (lane >= off) ws += x;
            }
            wsum[lane] = ws;
        }
        __syncthreads();
        int excl_warp = (w == 0) ? 0 : wsum[w - 1];
        int total = wsum[31];
        if (base + t < N_NODES) g_rowptr[base + t + 1] = carry_s + excl_warp + s;
        __syncthreads();
        if (t == 0) carry_s += total;
        __syncthreads();
    }
}

__global__ void cursor_kernel() {
    int i = blockIdx.x * blockDim.x + threadIdx.x;
    if (i < N_NODES) g_count[i] = g_rowptr[i];
}

__global__ void scatter_kernel(const int* __restrict__ src, const int* __restrict__ dst) {
    int e = blockIdx.x * blockDim.x + threadIdx.x;
    if (e < N_EDGES) {
        unsigned d = (unsigned)dst[e];
        unsigned s = (unsigned)src[e];
        if (d < N_NODES && s < N_NODES) {
            int pos = atomicAdd(&g_count[d], 1);
            if ((unsigned)pos < N_EDGES) g_esrc[pos] = (int)s;
        }
    }
}

// ---------------- mean aggregation: one warp per node ----------------
template <int HSEL>
__global__ void aggregate_kernel(const float* __restrict__ hext) {
    const float* __restrict__ h =
        (HSEL == 0) ? hext : ((HSEL == 1) ? (const float*)g_h1 : (const float*)g_h2);
    int warp = (blockIdx.x * blockDim.x + threadIdx.x) >> 5;
    int lane = threadIdx.x & 31;
    if (warp >= N_NODES) return;
    int beg = g_rowptr[warp];
    int end = g_rowptr[warp + 1];
    float ax = 0.f, ay = 0.f, az = 0.f, aw = 0.f;
    for (int i = beg; i < end; i++) {
        int s = g_esrc[i];
        float4 v = *reinterpret_cast<const float4*>(&h[(size_t)s * DIM + lane * 4]);
        ax += v.x; ay += v.y; az += v.z; aw += v.w;
    }
    float inv = (end > beg) ? (1.0f / (float)(end - beg)) : 0.0f;
    float4 r; r.x = ax * inv; r.y = ay * inv; r.z = az * inv; r.w = aw * inv;
    *reinterpret_cast<float4*>(&g_agg[(size_t)warp * DIM + lane * 4]) = r;
}

// ---------------- fused GEMM v4: K-tiled + packed f32x2 FFMA ----------------
// out[n][o] = act( sum_k [h|agg][n][k] * [Wself;Wneigh][k][o] + b[o] )
// Block: 256 threads (8 warps), tile J=64 nodes x OUT cols, K tiled by KT=64.
// Warp w owns cols [w*WC, (w+1)*WC); lane owns nodes {lane, lane+32}.
// Accumulators pack ADJACENT COLUMN PAIRS into f32x2; weights read as aligned
// u64 pairs from smem (warp-broadcast), activation broadcast-packed {a,a}.
template <int OUT, bool RELU, int HSEL, int DSEL>
__global__ __launch_bounds__(256)
void gemm_kernel(const float* __restrict__ hinext,
                 const float* __restrict__ Wself, const float* __restrict__ Wneigh,
                 const float* __restrict__ bias, float* __restrict__ outext) {
    const float* __restrict__ hin =
        (HSEL == 0) ? hinext : ((HSEL == 1) ? (const float*)g_h1 : (const float*)g_h2);
    float* __restrict__ out =
        (DSEL == 0) ? outext : ((DSEL == 1) ? (float*)g_h1 : (float*)g_h2);

    constexpr int KT   = 64;
    constexpr int J    = 64;
    constexpr int IPAD = J + 1;            // 65: conflict-free transpose
    constexpr int WC   = OUT / 8;          // cols per warp (16 / 8)
    constexpr int WP   = WC / 2;           // f32x2 col-pairs per warp (8 / 4)

    extern __shared__ float smem[];
    float* wT  = smem;                     // [KT][OUT]
    float* inT = smem + KT * OUT;          // [KT][IPAD]
    float* bs  = inT + KT * IPAD;          // [OUT]

    const int t     = threadIdx.x;
    const int lane  = t & 31;
    const int wid   = t >> 5;
    const int wcol0 = wid * WC;
    const int node0 = blockIdx.x * J;

    if (t < OUT) bs[t] = bias[t];

    u64 acc2[2][WP];
#pragma unroll
    for (int ni = 0; ni < 2; ni++)
#pragma unroll
        for (int p = 0; p < WP; p++) acc2[ni][p] = 0ull;

    for (int kt = 0; kt < 4; kt++) {
        const int k0 = kt * KT;
        // ---- load weight tile: contiguous rows k0..k0+63 of Wself or Wneigh ----
        {
            const float* Wrow = (k0 < 128) ? (Wself + (size_t)k0 * OUT)
                                           : (Wneigh + (size_t)(k0 - 128) * OUT);
            const float4* wsrc = reinterpret_cast<const float4*>(Wrow);
            float4* wdst = reinterpret_cast<float4*>(wT);
            constexpr int NW4 = KT * OUT / 4;
#pragma unroll
            for (int i = t; i < NW4; i += 256) wdst[i] = wsrc[i];
        }
        // ---- load input tile transposed: inT[k][j] = src[node0+j][k0+k] ----
        {
            const float* srcb = (k0 < 128) ? hin : (const float*)g_agg;
            const int koff = (k0 < 128) ? k0 : (k0 - 128);
            const float4 z4 = make_float4(0.f, 0.f, 0.f, 0.f);
#pragma unroll
            for (int i = t; i < J * (KT / 4); i += 256) {   // 64*16 = 1024
                int j  = i >> 4;
                int k4 = i & 15;
                int n  = node0 + j;
                float4 v = (n < N_NODES)
                    ? *reinterpret_cast<const float4*>(&srcb[(size_t)n * DIM + koff + k4 * 4])
                    : z4;
                int kb = k4 * 4;
                inT[(kb + 0) * IPAD + j] = v.x;
                inT[(kb + 1) * IPAD + j] = v.y;
                inT[(kb + 2) * IPAD + j] = v.z;
                inT[(kb + 3) * IPAD + j] = v.w;
            }
        }
        __syncthreads();

        // ---- compute: packed f32x2, column pairs ----
#pragma unroll 4
        for (int k = 0; k < KT; k++) {
            float a0 = inT[k * IPAD + lane];
            float a1 = inT[k * IPAD + 32 + lane];
            unsigned ai0 = __float_as_uint(a0), ai1 = __float_as_uint(a1);
            u64 a0p, a1p;
            asm("mov.b64 %0, {%1, %1};" : "=l"(a0p) : "r"(ai0));
            asm("mov.b64 %0, {%1, %1};" : "=l"(a1p) : "r"(ai1));
            const u64* w2 = reinterpret_cast<const u64*>(&wT[k * OUT + wcol0]);
#pragma unroll
            for (int p = 0; p < WP; p++) {
                u64 wv = w2[p];
                FMA_F32X2(acc2[0][p], a0p, wv);
                FMA_F32X2(acc2[1][p], a1p, wv);
            }
        }
        __syncthreads();
    }

    // ---- epilogue: unpack, bias + act + vectorized store ----
#pragma unroll
    for (int ni = 0; ni < 2; ni++) {
        int n = node0 + lane + ni * 32;
        if (n < N_NODES) {
#pragma unroll
            for (int c4 = 0; c4 < WC / 4; c4++) {
                unsigned u0, u1, u2, u3;
                asm("mov.b64 {%0, %1}, %2;" : "=r"(u0), "=r"(u1) : "l"(acc2[ni][c4 * 2]));
                asm("mov.b64 {%0, %1}, %2;" : "=r"(u2), "=r"(u3) : "l"(acc2[ni][c4 * 2 + 1]));
                float4 r;
                r.x = __uint_as_float(u0) + bs[wcol0 + c4 * 4 + 0];
                r.y = __uint_as_float(u1) + bs[wcol0 + c4 * 4 + 1];
                r.z = __uint_as_float(u2) + bs[wcol0 + c4 * 4 + 2];
                r.w = __uint_as_float(u3) + bs[wcol0 + c4 * 4 + 3];
                if (RELU) {
                    r.x = fmaxf(r.x, 0.f); r.y = fmaxf(r.y, 0.f);
                    r.z = fmaxf(r.z, 0.f); r.w = fmaxf(r.w, 0.f);
                }
                *reinterpret_cast<float4*>(&out[(size_t)n * OUT + wcol0 + c4 * 4]) = r;
            }
        }
    }
}

// ---------------- host launcher ----------------
extern "C" void kernel_launch(void* const* d_in, const int* in_sizes, int n_in,
                              void* d_out, int out_size) {
    // size-class input identification (ordering-agnostic)
    const float* x = nullptr;
    const int*   edge[2] = {nullptr, nullptr};
    const float* w16[4]  = {nullptr, nullptr, nullptr, nullptr};
    const float* w8[2]   = {nullptr, nullptr};
    const float* b128[2] = {nullptr, nullptr};
    const float* b2 = nullptr;
    int ne = 0, n16 = 0, n8 = 0, nb = 0;
    int x_slot = -1;

    for (int i = 0; i < n_in && i < 12; i++) {
        int sz = in_sizes[i];
        if (sz == N_NODES * DIM)      { x = (const float*)d_in[i]; x_slot = i; }
        else if (sz == N_EDGES)       { if (ne < 2)  edge[ne++] = (const int*)d_in[i]; }
        else if (sz == DIM * DIM)     { if (n16 < 4) w16[n16++] = (const float*)d_in[i]; }
        else if (sz == DIM * 64)      { if (n8 < 2)  w8[n8++]   = (const float*)d_in[i]; }
        else if (sz == DIM)           { if (nb < 2)  b128[nb++] = (const float*)d_in[i]; }
        else if (sz == 64)            { b2 = (const float*)d_in[i]; }
    }

    const float *Ws0, *Wn0, *b0, *Ws1, *Wn1, *b1, *Ws2, *Wn2;
    const int *src, *dst;
    if (x_slot == 0) {
        // insertion order: x, src, dst, W_self0, W_neigh0, b0, W_self1, ...
        src = edge[0]; dst = edge[1];
        Ws0 = w16[0]; Wn0 = w16[1]; Ws1 = w16[2]; Wn1 = w16[3];
        Ws2 = w8[0];  Wn2 = w8[1];
    } else {
        // lexicographic family: W_neigh* before W_self*, dst before src
        dst = edge[0]; src = edge[1];
        Wn0 = w16[0]; Wn1 = w16[1]; Ws0 = w16[2]; Ws1 = w16[3];
        Wn2 = w8[0];  Ws2 = w8[1];
    }
    b0 = b128[0]; b1 = b128[1];
    float* out = (float*)d_out;

    // smem sizes: wT(KT*OUT) + inT(KT*65) + bs(OUT), floats
    const int SMEM128 = (64 * 128 + 64 * 65 + 128) * 4;   // 49920 B
    const int SMEM64  = (64 * 64 + 64 * 65 + 64) * 4;     // 33280 B
    cudaFuncSetAttribute(gemm_kernel<128, true, 0, 1>,
                         cudaFuncAttributeMaxDynamicSharedMemorySize, SMEM128);
    cudaFuncSetAttribute(gemm_kernel<128, true, 1, 2>,
                         cudaFuncAttributeMaxDynamicSharedMemorySize, SMEM128);
    cudaFuncSetAttribute(gemm_kernel<64, false, 2, 0>,
                         cudaFuncAttributeMaxDynamicSharedMemorySize, SMEM64);

    // ---- CSR build (by dst) ----
    zero_count_kernel<<<(N_NODES + 255) / 256, 256>>>();
    hist_kernel<<<(N_EDGES + 255) / 256, 256>>>(dst);
    scan_kernel<<<1, 1024>>>();
    cursor_kernel<<<(N_NODES + 255) / 256, 256>>>();
    scatter_kernel<<<(N_EDGES + 255) / 256, 256>>>(src, dst);

    const int AGG_BLOCKS  = (N_NODES * 32 + 255) / 256;   // one warp per node
    const int GEMM_BLOCKS = (N_NODES + 63) / 64;

    // ---- layer 0: x -> g_h1 ----
    aggregate_kernel<0><<<AGG_BLOCKS, 256>>>(x);
    gemm_kernel<128, true, 0, 1><<<GEMM_BLOCKS, 256, SMEM128>>>(x, Ws0, Wn0, b0, nullptr);

    // ---- layer 1: g_h1 -> g_h2 ----
    aggregate_kernel<1><<<AGG_BLOCKS, 256>>>(nullptr);
    gemm_kernel<128, true, 1, 2><<<GEMM_BLOCKS, 256, SMEM128>>>(nullptr, Ws1, Wn1, b1, nullptr);

    // ---- layer 2: g_h2 -> out ----
    aggregate_kernel<2><<<AGG_BLOCKS, 256>>>(nullptr);
    gemm_kernel<64, false, 2, 0><<<GEMM_BLOCKS, 256, SMEM64>>>(nullptr, Ws2, Wn2, b2, out);
}